// round 4
// baseline (speedup 1.0000x reference)
#include <cuda_runtime.h>

// CTC loss forward, two-phase:
//   Phase 1 (gather): massively parallel gather + exp of emissions into a
//     compact L2-resident buffer:  ep[b][t][l] = exp(lp[t,b,c1(b,l)]),
//     bp[b][t] = exp(lp[t,b,blank]).  All scattered loads + MUFU here.
//   Phase 2 (scan): linear-domain CTC recursion, one warp per batch.
//     Per iter: 1 coalesced 128B load + 1 uniform load + shfl + ~7 flops.
//     Exact pow2 rescale every 4 steps via redux.sync.max.s32 on float bits.

constexpr int T_SZ  = 256;
constexpr int B_SZ  = 64;
constexpr int C_SZ  = 8000;
constexpr int L_MAX = 32;
constexpr int PF    = 8;    // emission prefetch depth (L2-resident source)

__device__ float g_ep[B_SZ][T_SZ][32];  // exp'd odd-state emissions, 2MB
__device__ float g_bp[B_SZ][T_SZ];      // exp'd blank emissions, 64KB
__device__ float g_loss[B_SZ];
__device__ int   g_count;

__device__ __forceinline__ int warp_max_s32(int v) {
    int r;
    asm volatile("redux.sync.max.s32 %0, %1, 0xffffffff;" : "=r"(r) : "r"(v));
    return r;
}

// ---------------- Phase 1: gather + exp ----------------
__global__ void __launch_bounds__(256)
ctc_gather_kernel(const float* __restrict__ lp,
                  const int*   __restrict__ targets,
                  const int*   __restrict__ tgt_len) {
    const int warp = (blockIdx.x * blockDim.x + threadIdx.x) >> 5;  // 0..B*T-1
    const int l    = threadIdx.x & 31;
    const int b    = warp >> 8;          // warp = b*256 + t
    const int t    = warp & 255;

    const int tl = tgt_len[b];
    const int c1 = (l < tl) ? targets[b * L_MAX + l] : 0;

    const float* base = lp + ((size_t)t * B_SZ + b) * C_SZ;
    g_ep[b][t][l] = __expf(__ldg(base + c1));
    if (l == 0) g_bp[b][t] = __expf(__ldg(base));
}

// ---------------- Phase 2: serial scan ----------------
__global__ void __launch_bounds__(32, 1)
ctc_scan_kernel(const float* __restrict__ lp,
                const int*   __restrict__ targets,
                const int*   __restrict__ in_len,
                const int*   __restrict__ tgt_len,
                float*       __restrict__ out) {
    const int b = blockIdx.x;
    const int l = threadIdx.x;

    const int tl   = tgt_len[b];
    const int last = in_len[b] - 1;             // in [128, 255]

    // label class for odd state 2l+1 (blank past target_len), skip flag
    const int  c1   = (l < tl) ? targets[b * L_MAX + l] : 0;
    const int  c1m  = __shfl_up_sync(0xffffffffu, c1, 1);
    const bool skip1 = (c1 != 0) && ((l == 0) || (c1 != c1m));

    // t = 0 init (prob domain) from raw log_probs
    const float* lp0 = lp + (size_t)b * C_SZ;
    float a0 = 0.f, a1 = 0.f, a2 = 0.f;
    if (l == 0) {
        a0 = __expf(lp0[0]);
        a1 = (tl > 0) ? __expf(lp0[c1]) : 0.f;
    }

    const float* epb = &g_ep[b][0][0];          // epb[t*32 + l]
    const float* bpb = &g_bp[b][0];             // bpb[t]

    // prefetch (already exp'd) emissions for t = 1..PF
    float e1[PF], eb[PF];
#pragma unroll
    for (int k = 0; k < PF; k++) {
        e1[k] = __ldg(epb + (1 + k) * 32 + l);
        eb[k] = __ldg(bpb + (1 + k));
    }

    int   se  = 0;                    // accumulated scale exponent (base 2)
    float fa0 = 0.f, fa1 = 0.f, fa2 = 0.f;
    int   fe  = 0;                    // snapshot of se at t == last

    #pragma unroll 8
    for (int t = 1; t <= 256; ++t) {
        const float p1 = e1[0];
        const float pb = eb[0];
#pragma unroll
        for (int k = 0; k < PF - 1; k++) { e1[k] = e1[k + 1]; eb[k] = eb[k + 1]; }
        {
            int tn = t + PF; tn = (tn > 255) ? 255 : tn;   // clamped dup loads, unused
            e1[PF - 1] = __ldg(epb + tn * 32 + l);
            eb[PF - 1] = __ldg(bpb + tn);
        }

        float pa1 = __shfl_up_sync(0xffffffffu, a1, 1);
        if (l == 0) pa1 = 0.f;

        const float s01 = a0 + pa1;
        const float n0  = s01 * pb;
        const float n1  = (a1 + (skip1 ? s01 : a0)) * p1;
        const float n2  = (a2 + a1) * pb;
        a0 = n0; a1 = n1; a2 = n2;

        if ((t & 3) == 0) {
            // warp-wide max alpha (nonnegative floats: int order == value order)
            const int mi  = warp_max_s32(__float_as_int(fmaxf(a0, fmaxf(a1, a2))));
            const int ebi = (mi >> 23) & 0xff;                   // biased exponent
            const float f = __int_as_float((286 - ebi) << 23);   // 2^(32 - E), exact
            a0 *= f; a1 *= f; a2 *= f;
            se += ebi - 159;                                     // E - 32
        }
        if (t == last) { fa0 = a0; fa1 = a1; fa2 = a2; fe = se; }
    }

    // final states: i_blank = 2*tl (even; state 64 lives in a2@lane31),
    //               i_char  = 2*tl - 1 (odd; a1 @ lane tl-1)
    const float vbl = __shfl_sync(0xffffffffu, fa0, tl & 31);
    const float vbh = __shfl_sync(0xffffffffu, fa2, 31);
    const float vb  = (tl >= 32) ? vbh : vbl;
    const int   icl = (tl > 0) ? (tl - 1) : 0;
    const float vc  = __shfl_sync(0xffffffffu, fa1, icl);
    const float tot = (tl > 0) ? (vb + vc) : vb;

    if (l == 0) {
        const float total_log = logf(tot) + (float)fe * 0.69314718055994531f;
        const int   denom     = (tl > 0) ? tl : 1;
        g_loss[b] = -total_log / (float)denom;
        __threadfence();
        const int old = atomicAdd(&g_count, 1);
        if (old == B_SZ - 1) {
            g_count = 0;            // reset for next graph replay
            __threadfence();
            float s = 0.f;
            for (int i = 0; i < B_SZ; i++) s += __ldcg((const float*)&g_loss[i]);
            out[0] = s / (float)B_SZ;
        }
    }
}

extern "C" void kernel_launch(void* const* d_in, const int* in_sizes, int n_in,
                              void* d_out, int out_size) {
    const float* log_probs  = (const float*)d_in[0];
    const int*   targets    = (const int*)d_in[1];
    const int*   input_len  = (const int*)d_in[2];
    const int*   target_len = (const int*)d_in[3];
    float* out = (float*)d_out;
    (void)in_sizes; (void)n_in; (void)out_size;

    // 16384 gather warps, 8 per block
    ctc_gather_kernel<<<(B_SZ * T_SZ) / 8, 256>>>(log_probs, targets, target_len);
    ctc_scan_kernel<<<B_SZ, 32>>>(log_probs, targets, input_len, target_len, out);
}

// round 5
// speedup vs baseline: 1.5087x; 1.5087x over previous
#include <cuda_runtime.h>

// CTC loss forward, single fused kernel, linear (probability) domain.
// One warp per batch element; lane l owns states 2l (blank, "e") and 2l+1
// (label l, "o"); lane 31 additionally owns state 64 ("a2").
//
// Two timesteps are fused per shuffle set: lane l rebuilds neighbor state
// o_t[l-1] locally from shfl'd alpha values + the neighbor's emission, then
// advances t and t+1 with pure FADD/FFMA/FMUL. Emissions (log space) are
// prefetched 24 steps ahead in a register ring (exp at consumption, off the
// dependent chain). Rescaling: every 4 steps, warp max via redux.sync.max.s32
// on float bits, exact power-of-two factor applied LAGGED at the next
// boundary so redux latency is hidden; integer exponent accumulated exactly.

constexpr int B_SZ  = 64;
constexpr int C_SZ  = 8000;
constexpr int L_MAX = 32;
constexpr int PF    = 24;   // prefetch ring depth, in timesteps

__device__ float g_loss[B_SZ];
__device__ int   g_count;

__device__ __forceinline__ int warp_max_s32(int v) {
    int r;
    asm volatile("redux.sync.max.s32 %0, %1, 0xffffffff;" : "=r"(r) : "r"(v));
    return r;
}
__device__ __forceinline__ float shup(float v, int d) {
    return __shfl_up_sync(0xffffffffu, v, d);
}

__global__ void __launch_bounds__(32, 1)
ctc_fused_kernel(const float* __restrict__ lp,
                 const int*   __restrict__ targets,
                 const int*   __restrict__ in_len,
                 const int*   __restrict__ tgt_len,
                 float*       __restrict__ out) {
    const int b = blockIdx.x;
    const int l = threadIdx.x;
    const size_t BC = (size_t)B_SZ * C_SZ;
    const float* lpb = lp + (size_t)b * C_SZ;   // lpb[t*BC + c]

    const int tl   = tgt_len[b];
    const int last = in_len[b] - 1;             // steps 1..last; last in [128,255]

    // label class for odd state 2l+1; skip flag; neighbor's skip flag
    const int  c1   = (l < tl) ? targets[b * L_MAX + l] : 0;
    const int  c1p  = __shfl_up_sync(0xffffffffu, c1, 1);
    const bool skip = (c1 != 0) && ((l == 0) || (c1 != c1p));
    const float skf  = skip ? 1.f : 0.f;
    const float skfm = shup(skf, 1);            // lane l-1's skip (l==0: masked below)
    const float m0   = (l == 0) ? 0.f : 1.f;
    const float m1   = (l <= 1) ? 0.f : 1.f;

    // t = 0 init (prob domain), pre-scaled by 2^80 for the lagged-rescale invariant
    float e = 0.f, o = 0.f, a2 = 0.f;
    if (l == 0) {
        e = __expf(lpb[0]) * 0x1p80f;
        o = (tl > 0) ? __expf(lpb[c1]) * 0x1p80f : 0.f;
    }
    int g = 80;                                 // stored = true * 2^g (exact)

    // prefetch ring (log-space emissions) for steps 1..PF
    float r1[PF], rb[PF];
#pragma unroll
    for (int k = 0; k < PF; k++) {
        const size_t off = (size_t)(1 + k) * BC;
        r1[k] = __ldg(lpb + off + c1);
        rb[k] = __ldg(lpb + off);
    }

    // neighbor emission (exp'd, masked) for the first fused pair
    float pmA = __expf(shup(r1[0], 1)) * m0;

    float fpend = 1.f;                          // lagged rescale factor
    int   fexp  = 0;

    const int nq = last >> 2;                   // quad bodies, 4 steps each
    int tnext = 1 + PF;                         // next step index to prefetch

    #pragma unroll 6
    for (int q = 0; q < nq; ++q) {
        // apply pending rescale (1 FMUL on chain), then measure for next apply
        e *= fpend; o *= fpend; a2 *= fpend; g += fexp;
        {
            const int mi = warp_max_s32(__float_as_int(fmaxf(e, fmaxf(o, a2))));
            int fx = 207 - ((mi >> 23) & 0xff);              // 80 - E, exact pow2
            fx = fx > 127 ? 127 : (fx < -126 ? -126 : fx);   // representable clamp
            fpend = __int_as_float((fx + 127) << 23);
            fexp  = fx;
        }

        // exp all 4 steps' emissions + neighbor emissions (all off-chain)
        const float p1s0 = __expf(r1[0]);
        const float p1s1 = __expf(r1[1]);
        const float p1s2 = __expf(r1[2]);
        const float p1s3 = __expf(r1[3]);
        const float pbs0 = __expf(rb[0]);
        const float pbs1 = __expf(rb[1]);
        const float pbs2 = __expf(rb[2]);
        const float pbs3 = __expf(rb[3]);
        const float pmB  = __expf(shup(r1[2], 1)) * m0;   // pair B's neighbor em
        const float pmN  = __expf(shup(r1[4], 1)) * m0;   // next body's pair A

        // fused pair A: steps t, t+1
        {
            const float x1  = shup(o, 1) * m0;            // o_{t-1}[l-1]
            const float x2  = shup(o, 2) * m1;            // o_{t-1}[l-2]
            const float y1  = shup(e, 1);                 // e_{t-1}[l-1] (pmA masks l==0)
            const float otm = ((x1 + y1) + skfm * x2) * pmA;   // o_t[l-1]
            const float et  = (e + x1) * pbs0;
            const float ot  = ((o + e) + skf * x1) * p1s0;
            const float a2t = (a2 + o) * pbs0;
            e  = (et + otm) * pbs1;
            o  = ((ot + et) + skf * otm) * p1s1;
            a2 = (a2t + ot) * pbs1;
        }
        // fused pair B: steps t+2, t+3
        {
            const float x1  = shup(o, 1) * m0;
            const float x2  = shup(o, 2) * m1;
            const float y1  = shup(e, 1);
            const float otm = ((x1 + y1) + skfm * x2) * pmB;
            const float et  = (e + x1) * pbs2;
            const float ot  = ((o + e) + skf * x1) * p1s2;
            const float a2t = (a2 + o) * pbs2;
            e  = (et + otm) * pbs3;
            o  = ((ot + et) + skf * otm) * p1s3;
            a2 = (a2t + ot) * pbs3;
        }
        pmA = pmN;

        // rotate ring by 4 and refill (clamped dup loads past T-1, values unused)
#pragma unroll
        for (int k = 0; k < PF - 4; k++) { r1[k] = r1[k + 4]; rb[k] = rb[k + 4]; }
#pragma unroll
        for (int j = 0; j < 4; j++) {
            int tt = tnext + j; tt = (tt > 255) ? 255 : tt;
            const size_t off = (size_t)tt * BC;
            r1[PF - 4 + j] = __ldg(lpb + off + c1);
            rb[PF - 4 + j] = __ldg(lpb + off);
        }
        tnext += 4;
    }

    // epilogue: up to 3 remaining single steps (4*nq+1 .. last)
    const int rem = last - (nq << 2);
#pragma unroll
    for (int j = 0; j < 3; j++) {
        if (j < rem) {
            const float p1 = __expf(r1[j]);
            const float pb = __expf(rb[j]);
            const float pa = shup(o, 1) * m0;
            const float en = (e + pa) * pb;
            const float on = ((o + e) + skf * pa) * p1;
            const float an = (a2 + o) * pb;
            e = en; o = on; a2 = an;
        }
    }

    // final states: i_blank = 2*tl (e @ lane tl, or a2 @ lane 31 if tl==32),
    //               i_char  = 2*tl-1 (o @ lane tl-1)
    const float vbl = __shfl_sync(0xffffffffu, e, tl & 31);
    const float vbh = __shfl_sync(0xffffffffu, a2, 31);
    const float vb  = (tl >= 32) ? vbh : vbl;
    const int   icl = (tl > 0) ? (tl - 1) : 0;
    const float vc  = __shfl_sync(0xffffffffu, o, icl);
    const float tot = (tl > 0) ? (vb + vc) : vb;

    if (l == 0) {
        const float total_log = logf(tot) - (float)g * 0.69314718055994531f;
        const int   denom     = (tl > 0) ? tl : 1;
        g_loss[b] = -total_log / (float)denom;
        __threadfence();
        const int old = atomicAdd(&g_count, 1);
        if (old == B_SZ - 1) {
            g_count = 0;            // reset for next graph replay
            __threadfence();
            float s = 0.f;
            for (int i = 0; i < B_SZ; i++) s += __ldcg((const float*)&g_loss[i]);
            out[0] = s / (float)B_SZ;
        }
    }
}

extern "C" void kernel_launch(void* const* d_in, const int* in_sizes, int n_in,
                              void* d_out, int out_size) {
    const float* log_probs  = (const float*)d_in[0];
    const int*   targets    = (const int*)d_in[1];
    const int*   input_len  = (const int*)d_in[2];
    const int*   target_len = (const int*)d_in[3];
    float* out = (float*)d_out;
    (void)in_sizes; (void)n_in; (void)out_size;

    ctc_fused_kernel<<<B_SZ, 32>>>(log_probs, targets, input_len, target_len, out);
}